// round 3
// baseline (speedup 1.0000x reference)
#include <cuda_runtime.h>

// Fused masked-scale MSE, round 3:
//  - plain LDG (revert __ldcs: R2 showed it cost ~4% DRAM throughput)
//  - compile-time stride => independent unrolled addresses, no carried index chain
//  - fused last-block-ticket finish (saved ~1.3us launch overhead in R2; keep)

constexpr int THREADS = 256;
constexpr int BLOCKS  = 2048;
constexpr int STRIDE  = THREADS * BLOCKS;   // 524288

__device__ float        g_partial = 0.0f;
__device__ unsigned int g_ticket  = 0u;

__device__ __forceinline__ float elem_term(float n, float l) {
    // labels are exactly 0.0f, 1.0f, or 2.0f
    float sn = (l == 1.0f) ? 10.0f : ((l == 2.0f) ? 5.0f : 1.0f);
    float sl = (l == 0.0f) ? 1.0f : 10.0f;
    float d = fmaf(n, sn, -l * sl);
    return d * d;
}

__global__ void __launch_bounds__(THREADS)
mse_loss_kernel(const float4* __restrict__ n4,
                const float4* __restrict__ l4,
                float* __restrict__ out,
                int n_vec,        // number of float4 elements
                int per_thread,   // full iterations per thread (exact part)
                float inv_n)
{
    const int tid = blockIdx.x * THREADS + threadIdx.x;

    float acc = 0.0f;

    // Addresses are tid + k*STRIDE with STRIDE a compile-time constant:
    // each unrolled copy has an independent immediate-offset address,
    // so loads front-batch (2 loads x 2 arrays x 2 unrolled = MLP 8).
    #pragma unroll 2
    for (int k = 0; k + 1 < per_thread; k += 2) {
        float4 a0 = n4[tid + (k + 0) * STRIDE];
        float4 b0 = l4[tid + (k + 0) * STRIDE];
        float4 a1 = n4[tid + (k + 1) * STRIDE];
        float4 b1 = l4[tid + (k + 1) * STRIDE];
        acc += elem_term(a0.x, b0.x);
        acc += elem_term(a0.y, b0.y);
        acc += elem_term(a0.z, b0.z);
        acc += elem_term(a0.w, b0.w);
        acc += elem_term(a1.x, b1.x);
        acc += elem_term(a1.y, b1.y);
        acc += elem_term(a1.z, b1.z);
        acc += elem_term(a1.w, b1.w);
    }

    // odd-count / remainder coverage (not taken on 4096x8192)
    int rem = per_thread & ~1;
    for (int i = tid + rem * STRIDE; i < n_vec; i += STRIDE) {
        float4 a = n4[i];
        float4 b = l4[i];
        acc += elem_term(a.x, b.x);
        acc += elem_term(a.y, b.y);
        acc += elem_term(a.z, b.z);
        acc += elem_term(a.w, b.w);
    }

    // warp reduction
    #pragma unroll
    for (int off = 16; off > 0; off >>= 1)
        acc += __shfl_down_sync(0xffffffffu, acc, off);

    __shared__ float warp_sums[THREADS / 32];
    int lane = threadIdx.x & 31;
    int wid  = threadIdx.x >> 5;
    if (lane == 0) warp_sums[wid] = acc;
    __syncthreads();

    if (wid == 0) {
        float v = (lane < THREADS / 32) ? warp_sums[lane] : 0.0f;
        #pragma unroll
        for (int off = 4; off > 0; off >>= 1)
            v += __shfl_down_sync(0xffffffffu, v, off);

        if (lane == 0) {
            atomicAdd(&g_partial, v);
            __threadfence();
            unsigned int ticket = atomicAdd(&g_ticket, 1u);
            if (ticket == gridDim.x - 1) {
                out[0] = g_partial * inv_n;
                g_partial = 0.0f;
                g_ticket  = 0u;
            }
        }
    }
}

extern "C" void kernel_launch(void* const* d_in, const int* in_sizes, int n_in,
                              void* d_out, int out_size)
{
    const float4* norms  = (const float4*)d_in[0];
    const float4* labels = (const float4*)d_in[1];
    float* out = (float*)d_out;

    int n_elems = in_sizes[0];          // 33554432
    int n_vec   = n_elems / 4;          // 8388608
    float inv_n = 1.0f / (float)n_elems;

    int per_thread = n_vec / STRIDE;    // 16 on this shape

    mse_loss_kernel<<<BLOCKS, THREADS>>>(norms, labels, out,
                                         n_vec, per_thread, inv_n);
}

// round 4
// speedup vs baseline: 1.0309x; 1.0309x over previous
#include <cuda_runtime.h>

// Fused masked-scale MSE, round 4:
//   = R1 mainloop verbatim (measured best: 42.0us kernel, DRAM 81.7%, regs 32,
//     occ 88.3%) + the R2-validated last-block-ticket finish (saves ~1.3us of
//     launch overhead vs a separate zero-init kernel).
//   R2 (__ldcs, carried int index) and R3 (const-stride imm offsets, regs 36)
//   both regressed DRAM throughput; reverted.

__device__ float        g_partial = 0.0f;
__device__ unsigned int g_ticket  = 0u;

__device__ __forceinline__ float elem_term(float n, float l) {
    // labels are exactly 0.0f, 1.0f, or 2.0f
    float sn = (l == 1.0f) ? 10.0f : ((l == 2.0f) ? 5.0f : 1.0f);
    float sl = (l == 0.0f) ? 1.0f : 10.0f;
    float d = fmaf(n, sn, -l * sl);
    return d * d;
}

__global__ void __launch_bounds__(256)
mse_loss_kernel(const float* __restrict__ norms,
                const float* __restrict__ labels,
                float* __restrict__ out,
                long long n_vec,      // number of float4 elements
                float inv_n)
{
    const float4* __restrict__ n4 = reinterpret_cast<const float4*>(norms);
    const float4* __restrict__ l4 = reinterpret_cast<const float4*>(labels);

    long long idx = (long long)blockIdx.x * blockDim.x + threadIdx.x;
    long long stride = (long long)gridDim.x * blockDim.x;

    float acc = 0.0f;
    // 2x unroll of the grid-stride loop: front-batches 4 float4 loads
    // per iteration for high MLP.  (R1 mainloop, measured best.)
    for (long long i = idx; i < n_vec; i += 2 * stride) {
        float4 a0 = n4[i];
        float4 b0 = l4[i];
        long long j = i + stride;
        float4 a1, b1;
        bool have2 = (j < n_vec);
        if (have2) { a1 = n4[j]; b1 = l4[j]; }

        acc += elem_term(a0.x, b0.x);
        acc += elem_term(a0.y, b0.y);
        acc += elem_term(a0.z, b0.z);
        acc += elem_term(a0.w, b0.w);
        if (have2) {
            acc += elem_term(a1.x, b1.x);
            acc += elem_term(a1.y, b1.y);
            acc += elem_term(a1.z, b1.z);
            acc += elem_term(a1.w, b1.w);
        }
    }

    // warp reduction
    #pragma unroll
    for (int off = 16; off > 0; off >>= 1)
        acc += __shfl_down_sync(0xffffffffu, acc, off);

    __shared__ float warp_sums[8];
    int lane = threadIdx.x & 31;
    int wid  = threadIdx.x >> 5;
    if (lane == 0) warp_sums[wid] = acc;
    __syncthreads();

    if (wid == 0) {
        float v = (lane < (int)(blockDim.x >> 5)) ? warp_sums[lane] : 0.0f;
        #pragma unroll
        for (int off = 4; off > 0; off >>= 1)
            v += __shfl_down_sync(0xffffffffu, v, off);

        if (lane == 0) {
            atomicAdd(&g_partial, v);
            __threadfence();
            unsigned int ticket = atomicAdd(&g_ticket, 1u);
            if (ticket == gridDim.x - 1) {
                // all block partials visible; finish and reset for next replay
                out[0] = g_partial * inv_n;
                g_partial = 0.0f;
                g_ticket  = 0u;
            }
        }
    }
}

extern "C" void kernel_launch(void* const* d_in, const int* in_sizes, int n_in,
                              void* d_out, int out_size)
{
    const float* norms  = (const float*)d_in[0];
    const float* labels = (const float*)d_in[1];
    float* out = (float*)d_out;

    long long n_elems = (long long)in_sizes[0];   // 33554432
    long long n_vec = n_elems / 4;                // 8388608
    float inv_n = 1.0f / (float)n_elems;

    const int threads = 256;
    const int blocks  = 2048;

    mse_loss_kernel<<<blocks, threads>>>(norms, labels, out, n_vec, inv_n);
}

// round 5
// speedup vs baseline: 1.0370x; 1.0059x over previous
#include <cuda_runtime.h>

// Fused masked-scale MSE, round 5:
//   R4 structure (measured best: 42.75us kernel, DRAM 80.4%) with exactly ONE
//   change: int32 indexing instead of long long. n_vec=8388608 fits easily.
//   R2/R3 never tested this in isolation (they also changed loop shape/unroll).

__device__ float        g_partial = 0.0f;
__device__ unsigned int g_ticket  = 0u;

__device__ __forceinline__ float elem_term(float n, float l) {
    // labels are exactly 0.0f, 1.0f, or 2.0f
    float sn = (l == 1.0f) ? 10.0f : ((l == 2.0f) ? 5.0f : 1.0f);
    float sl = (l == 0.0f) ? 1.0f : 10.0f;
    float d = fmaf(n, sn, -l * sl);
    return d * d;
}

__global__ void __launch_bounds__(256)
mse_loss_kernel(const float* __restrict__ norms,
                const float* __restrict__ labels,
                float* __restrict__ out,
                int n_vec,      // number of float4 elements
                float inv_n)
{
    const float4* __restrict__ n4 = reinterpret_cast<const float4*>(norms);
    const float4* __restrict__ l4 = reinterpret_cast<const float4*>(labels);

    int idx = blockIdx.x * blockDim.x + threadIdx.x;
    int stride = gridDim.x * blockDim.x;

    float acc = 0.0f;
    // 2x unroll of the grid-stride loop: front-batches 4 float4 loads
    // per iteration for high MLP.  (R1/R4 mainloop shape, measured best.)
    for (int i = idx; i < n_vec; i += 2 * stride) {
        float4 a0 = n4[i];
        float4 b0 = l4[i];
        int j = i + stride;
        float4 a1, b1;
        bool have2 = (j < n_vec);
        if (have2) { a1 = n4[j]; b1 = l4[j]; }

        acc += elem_term(a0.x, b0.x);
        acc += elem_term(a0.y, b0.y);
        acc += elem_term(a0.z, b0.z);
        acc += elem_term(a0.w, b0.w);
        if (have2) {
            acc += elem_term(a1.x, b1.x);
            acc += elem_term(a1.y, b1.y);
            acc += elem_term(a1.z, b1.z);
            acc += elem_term(a1.w, b1.w);
        }
    }

    // warp reduction
    #pragma unroll
    for (int off = 16; off > 0; off >>= 1)
        acc += __shfl_down_sync(0xffffffffu, acc, off);

    __shared__ float warp_sums[8];
    int lane = threadIdx.x & 31;
    int wid  = threadIdx.x >> 5;
    if (lane == 0) warp_sums[wid] = acc;
    __syncthreads();

    if (wid == 0) {
        float v = (lane < (int)(blockDim.x >> 5)) ? warp_sums[lane] : 0.0f;
        #pragma unroll
        for (int off = 4; off > 0; off >>= 1)
            v += __shfl_down_sync(0xffffffffu, v, off);

        if (lane == 0) {
            atomicAdd(&g_partial, v);
            __threadfence();
            unsigned int ticket = atomicAdd(&g_ticket, 1u);
            if (ticket == gridDim.x - 1) {
                // all block partials visible; finish and reset for next replay
                out[0] = g_partial * inv_n;
                g_partial = 0.0f;
                g_ticket  = 0u;
            }
        }
    }
}

extern "C" void kernel_launch(void* const* d_in, const int* in_sizes, int n_in,
                              void* d_out, int out_size)
{
    const float* norms  = (const float*)d_in[0];
    const float* labels = (const float*)d_in[1];
    float* out = (float*)d_out;

    int n_elems = in_sizes[0];        // 33554432
    int n_vec   = n_elems / 4;        // 8388608
    float inv_n = 1.0f / (float)n_elems;

    const int threads = 256;
    const int blocks  = 2048;

    mse_loss_kernel<<<blocks, threads>>>(norms, labels, out, n_vec, inv_n);
}